// round 16
// baseline (speedup 1.0000x reference)
#include <cuda_runtime.h>
#include <cuda_bf16.h>
#include <mma.h>
#include <cstdint>

using namespace nvcuda;

#define BB   256
#define LL   512
#define FF   64
#define LF   32768
#define NTOT 8388608
#define HH   128
#define H2   256
#define ND   64

// ---------------- device globals ----------------
__device__ __align__(16) uint32_t g_h3b[BB * (H2 / 2)];   // h3 bf16: [256 rows][256]
__device__ float  g_scale[BB * FF];
__device__ float  g_freq[NTOT];
__device__ float  g_gm[NTOT];
__device__ float  g_gn[NTOT];
__device__ int    g_wp[BB], g_sh[BB];

// ---------------- threefry2x32 (JAX) ----------------
__device__ __forceinline__ uint2 tf2x32(uint32_t k0, uint32_t k1, uint32_t x0, uint32_t x1) {
    uint32_t k2 = k0 ^ k1 ^ 0x1BD11BDAu;
    x0 += k0; x1 += k1;
#define TFR(r) { x0 += x1; x1 = (x1 << (r)) | (x1 >> (32 - (r))); x1 ^= x0; }
    TFR(13) TFR(15) TFR(26) TFR(6)
    x0 += k1; x1 += k2 + 1u;
    TFR(17) TFR(29) TFR(16) TFR(24)
    x0 += k2; x1 += k0 + 2u;
    TFR(13) TFR(15) TFR(26) TFR(6)
    x0 += k0; x1 += k1 + 3u;
    TFR(17) TFR(29) TFR(16) TFR(24)
    x0 += k1; x1 += k2 + 4u;
    TFR(13) TFR(15) TFR(26) TFR(6)
    x0 += k2; x1 += k0 + 5u;
#undef TFR
    return make_uint2(x0, x1);
}
__device__ __forceinline__ uint32_t tf_bits(uint2 key, uint32_t e) {
    uint2 r = tf2x32(key.x, key.y, 0u, e);
    return r.x ^ r.y;
}
__device__ __forceinline__ float u01_from_bits(uint32_t bits) {
    return __uint_as_float((bits >> 9) | 0x3f800000u) - 1.0f;
}
__device__ __forceinline__ float tf_normal(uint2 key, uint32_t e) {
    float u = u01_from_bits(tf_bits(key, e));
    const float lo = -0.99999994f;
    float v = u * 2.0f + lo;
    v = fmaxf(lo, v);
    return 1.4142135623730951f * erfinvf(v);
}
__device__ __forceinline__ float sigmf(float x)  { return 1.0f / (1.0f + expf(-x)); }
__device__ __forceinline__ float softplusf(float x) { return fmaxf(x, 0.0f) + log1pf(expf(-fabsf(x))); }
__device__ __forceinline__ float sigmf_fast(float x)  { return __fdividef(1.0f, 1.0f + __expf(-x)); }
__device__ __forceinline__ float softplusf_fast(float x) { return fmaxf(x, 0.0f) + __logf(1.0f + __expf(-fabsf(x))); }

__device__ __forceinline__ float2 cadd(float2 a, float2 b) { return make_float2(a.x + b.x, a.y + b.y); }
__device__ __forceinline__ float2 csub(float2 a, float2 b) { return make_float2(a.x - b.x, a.y - b.y); }
__device__ __forceinline__ float2 cmul(float2 a, float2 w) { return make_float2(a.x * w.x - a.y * w.y, a.x * w.y + a.y * w.x); }
__device__ __forceinline__ float2 cmulc(float2 w, float2 b) { return make_float2(w.x * b.x + w.y * b.y, w.x * b.y - w.y * b.x); }

// ---------------- kernel 1: MLP (blocks 0..255) + setup (block 256) ---------
__global__ __launch_bounds__(256) void mlp_setup(
    const float* __restrict__ w1, const float* __restrict__ b1,
    const float* __restrict__ w2, const float* __restrict__ b2,
    const float* __restrict__ w3, const float* __restrict__ b3,
    const float* __restrict__ ws, const float* __restrict__ bs,
    const float* __restrict__ psh, const float* __restrict__ psc)
{
    __shared__ float zb[ND], h1b[HH], h2b[H2], h3b[H2];
    int tid = threadIdx.x;

    if (blockIdx.x >= 256) {
        // ------- setup: wp/sh randints -------
        float ss_ = sigmf(*psh);
        int ws_ = (int)(51.2f * ss_);
        uint2 kwp = tf2x32(0u, 42u, 0u, 2u);
        uint2 ksh = tf2x32(0u, 42u, 0u, 3u);
        uint2 skwp1 = tf2x32(kwp.x, kwp.y, 0u, 0u);
        uint2 skwp2 = tf2x32(kwp.x, kwp.y, 0u, 1u);
        uint2 sksh1 = tf2x32(ksh.x, ksh.y, 0u, 0u);
        uint2 sksh2 = tf2x32(ksh.x, ksh.y, 0u, 1u);
        {
            uint32_t span = (uint32_t)max(1, (512 - ws_) - ws_);
            uint32_t mult = 65536u % span; mult = (mult * mult) % span;
            uint32_t hi = tf_bits(skwp1, (uint32_t)tid);
            uint32_t lo = tf_bits(skwp2, (uint32_t)tid);
            uint32_t off = ((hi % span) * mult + (lo % span)) % span;
            g_wp[tid] = ws_ + (int)off;
        }
        {
            uint32_t span = (uint32_t)(2 * ws_ + 1); if (span == 0u) span = 1u;
            uint32_t mult = 65536u % span; mult = (mult * mult) % span;
            uint32_t hi = tf_bits(sksh1, (uint32_t)tid);
            uint32_t lo = tf_bits(sksh2, (uint32_t)tid);
            uint32_t off = ((hi % span) * mult + (lo % span)) % span;
            g_sh[tid] = -ws_ + (int)off;
        }
        return;
    }

    // ------- MLP path -------
    int m = blockIdx.x, t = tid;
    uint2 kz = tf2x32(0u, 42u, 0u, 0u);
    if (t < ND) zb[t] = tf_normal(kz, (uint32_t)(m * ND + t));
    __syncthreads();
    if (t < HH) {
        float acc = b1[t];
#pragma unroll 8
        for (int k = 0; k < ND; k++) acc = fmaf(zb[k], w1[k * HH + t], acc);
        h1b[t] = acc > 0.0f ? acc : 0.2f * acc;
    }
    __syncthreads();
    {
        float acc = b2[t];
#pragma unroll 8
        for (int k = 0; k < HH; k++) acc = fmaf(h1b[k], w2[k * H2 + t], acc);
        h2b[t] = acc > 0.0f ? acc : 0.2f * acc;
    }
    __syncthreads();
    {
        float acc = b3[t];
#pragma unroll 8
        for (int k = 0; k < H2; k++) acc = fmaf(h2b[k], w3[k * H2 + t], acc);
        h3b[t] = acc > 0.0f ? acc : 0.2f * acc;
    }
    __syncthreads();
    if (t < H2 / 2) {
        __nv_bfloat162 p = __floats2bfloat162_rn(h3b[2 * t], h3b[2 * t + 1]);
        g_h3b[m * (H2 / 2) + t] = *reinterpret_cast<uint32_t*>(&p);
    }
    if (t < FF) {
        float s_scale = sigmf(*psc);
        float acc = bs[t];
#pragma unroll 8
        for (int k = 0; k < H2; k++) acc = fmaf(h3b[k], ws[k * FF + t], acc);
        g_scale[m * FF + t] = 1.0f + (softplusf(acc) - 0.5f) * 0.2f * s_scale;
    }
}

// ---------------- kernel 2: combined GEMM (blocks 0..511) + FFT (512..2559) -
#define BPLD 72
#define PAN_BYTES 36864
#define DYN_SMEM  (2 * PAN_BYTES)       // 73728 B; FFT path uses 38912 of it

__global__ __launch_bounds__(512, 2) void fft_gemm(
    const float* __restrict__ x,
    const float* __restrict__ wm, const float* __restrict__ wn,
    const float* __restrict__ psh)
{
    extern __shared__ char smem[];
    int tid = threadIdx.x;

    if (blockIdx.x < 512) {
        // ================= GEMM path =================
        __nv_bfloat16* Bm = reinterpret_cast<__nv_bfloat16*>(smem);
        __nv_bfloat16* Bn = reinterpret_cast<__nv_bfloat16*>(smem + PAN_BYTES);
        int wid = tid >> 5;
        int n0 = blockIdx.x * 64;
        const __nv_bfloat16* Ag = reinterpret_cast<const __nv_bfloat16*>(g_h3b);

#pragma unroll
        for (int i = 0; i < 4; i++) {
            int u = i * 512 + tid;
            int r = u >> 3, c = (u & 7) * 8;
            {
                const float4* src = reinterpret_cast<const float4*>(wm + (size_t)r * LF + n0 + c);
                float4 v0 = src[0], v1 = src[1];
                __nv_bfloat162 p0 = __floats2bfloat162_rn(v0.x, v0.y);
                __nv_bfloat162 p1 = __floats2bfloat162_rn(v0.z, v0.w);
                __nv_bfloat162 p2 = __floats2bfloat162_rn(v1.x, v1.y);
                __nv_bfloat162 p3 = __floats2bfloat162_rn(v1.z, v1.w);
                uint4 pk = make_uint4(*reinterpret_cast<uint32_t*>(&p0), *reinterpret_cast<uint32_t*>(&p1),
                                      *reinterpret_cast<uint32_t*>(&p2), *reinterpret_cast<uint32_t*>(&p3));
                *reinterpret_cast<uint4*>(Bm + r * BPLD + c) = pk;
            }
            {
                const float4* src = reinterpret_cast<const float4*>(wn + (size_t)r * LF + n0 + c);
                float4 v0 = src[0], v1 = src[1];
                __nv_bfloat162 p0 = __floats2bfloat162_rn(v0.x, v0.y);
                __nv_bfloat162 p1 = __floats2bfloat162_rn(v0.z, v0.w);
                __nv_bfloat162 p2 = __floats2bfloat162_rn(v1.x, v1.y);
                __nv_bfloat162 p3 = __floats2bfloat162_rn(v1.z, v1.w);
                uint4 pk = make_uint4(*reinterpret_cast<uint32_t*>(&p0), *reinterpret_cast<uint32_t*>(&p1),
                                      *reinterpret_cast<uint32_t*>(&p2), *reinterpret_cast<uint32_t*>(&p3));
                *reinterpret_cast<uint4*>(Bn + r * BPLD + c) = pk;
            }
        }
        __syncthreads();

#pragma unroll
        for (int gsel = 0; gsel < 2; gsel++) {
            const __nv_bfloat16* Bt = gsel ? Bn : Bm;
            float* dst = gsel ? g_gn : g_gm;
            wmma::fragment<wmma::accumulator, 16, 16, 16, float> acc[4];
#pragma unroll
            for (int ni = 0; ni < 4; ni++) wmma::fill_fragment(acc[ni], 0.0f);
#pragma unroll
            for (int kt = 0; kt < 16; kt++) {
                wmma::fragment<wmma::matrix_a, 16, 16, 16, __nv_bfloat16, wmma::row_major> af;
                wmma::load_matrix_sync(af, Ag + (size_t)(wid * 16) * H2 + kt * 16, H2);
#pragma unroll
                for (int ni = 0; ni < 4; ni++) {
                    wmma::fragment<wmma::matrix_b, 16, 16, 16, __nv_bfloat16, wmma::row_major> bf;
                    wmma::load_matrix_sync(bf, Bt + (size_t)kt * 16 * BPLD + ni * 16, BPLD);
                    wmma::mma_sync(acc[ni], af, bf, acc[ni]);
                }
            }
#pragma unroll
            for (int ni = 0; ni < 4; ni++)
                wmma::store_matrix_sync(dst + (size_t)(wid * 16) * LF + n0 + ni * 16,
                                        acc[ni], LF, wmma::mem_row_major);
        }
        return;
    }

    // ================= FFT path (512 threads) =================
    float2 (*s)[9] = reinterpret_cast<float2(*)[9]>(smem);            // [512][9]
    float2* tw = reinterpret_cast<float2*>(smem + 36864);             // [256]

    float ss_ = sigmf(*psh);
    float smix = 1.0f - ss_;
    float ratio = fminf(smix * 0.1f, 0.5f);
    uint2 kf = tf2x32(0u, 42u, 0u, 4u);

    int bidx = blockIdx.x - 512;
    int b = bidx >> 3;
    int f0 = (bidx & 7) * 8;
    const float* xp = x + (size_t)b * LF + f0;
    if (tid < 256) {
        float sv, cv;
        sincosf(-6.283185307179586f * (float)tid / 512.0f, &sv, &cv);
        tw[tid] = make_float2(cv, sv);
    }
#pragma unroll
    for (int it = 0; it < 2; it++) {
        int c4 = it * 512 + tid;
        int l = c4 >> 1, q = (c4 & 1) * 4;
        float4 v = *reinterpret_cast<const float4*>(xp + (size_t)l * FF + q);
        s[l][q + 0] = make_float2(v.x, 0.0f);
        s[l][q + 1] = make_float2(v.y, 0.0f);
        s[l][q + 2] = make_float2(v.z, 0.0f);
        s[l][q + 3] = make_float2(v.w, 0.0f);
    }
    __syncthreads();

    // forward DIF radix-8 rounds
#pragma unroll
    for (int st = 0; st < 9; st += 3) {
        const int h4 = 64 >> st;
        {
            int u = tid;                      // 512 units: 64 groups x 8 cols
            int ff = u & 7, gi = u >> 3;
            int k = gi & (h4 - 1);
            int g = gi >> (6 - st);
            int p = (g << (9 - st)) + k;
            float2 v[8];
#pragma unroll
            for (int j = 0; j < 8; j++) v[j] = s[p + j * h4][ff];
#pragma unroll
            for (int j = 0; j < 4; j++) {
                float2 a = v[j], bb = v[j + 4];
                v[j]     = cadd(a, bb);
                v[j + 4] = cmul(csub(a, bb), tw[(k + j * h4) << st]);
            }
#pragma unroll
            for (int jj = 0; jj < 4; jj++) {
                int j = (jj >> 1) * 4 + (jj & 1);
                float2 a = v[j], bb = v[j + 2];
                v[j]     = cadd(a, bb);
                v[j + 2] = cmul(csub(a, bb), tw[(k + (j & 1) * h4) << (st + 1)]);
            }
#pragma unroll
            for (int jj = 0; jj < 4; jj++) {
                int j = jj * 2;
                float2 a = v[j], bb = v[j + 1];
                v[j]     = cadd(a, bb);
                v[j + 1] = cmul(csub(a, bb), tw[k << (st + 2)]);
            }
#pragma unroll
            for (int j = 0; j < 8; j++) s[p + j * h4][ff] = v[j];
        }
        __syncthreads();
    }

    // inverse DIT radix-8 rounds; mask fused into first round's load
#pragma unroll
    for (int st = 0; st < 9; st += 3) {
        const int h = 1 << st;
        {
            int u = tid;
            int ff = u & 7, gi = u >> 3;
            int k = gi & (h - 1);
            int g = gi >> st;
            int p = (g << (st + 3)) + k;
            float2 v[8];
#pragma unroll
            for (int j = 0; j < 8; j++) v[j] = s[p + j * h][ff];
            if (st == 0) {
#pragma unroll
                for (int j = 0; j < 8; j++) {
                    int q = p + j;
                    int jn = (int)(__brev((unsigned)q) >> 23);
                    uint32_t e = (uint32_t)b * LF + (uint32_t)jn * FF + (uint32_t)(f0 + ff);
                    if (!(u01_from_bits(tf_bits(kf, e)) > ratio)) v[j] = make_float2(0.0f, 0.0f);
                }
            }
#pragma unroll
            for (int jj = 0; jj < 4; jj++) {
                int j = jj * 2;
                float2 a = v[j];
                float2 t = cmulc(tw[k << (8 - st)], v[j + 1]);
                v[j]     = cadd(a, t);
                v[j + 1] = csub(a, t);
            }
#pragma unroll
            for (int jj = 0; jj < 4; jj++) {
                int j = (jj >> 1) * 4 + (jj & 1);
                float2 a = v[j];
                float2 t = cmulc(tw[(k + (j & 1) * h) << (7 - st)], v[j + 2]);
                v[j]     = cadd(a, t);
                v[j + 2] = csub(a, t);
            }
#pragma unroll
            for (int j = 0; j < 4; j++) {
                float2 a = v[j];
                float2 t = cmulc(tw[(k + j * h) << (6 - st)], v[j + 4]);
                v[j]     = cadd(a, t);
                v[j + 4] = csub(a, t);
            }
#pragma unroll
            for (int j = 0; j < 8; j++) s[p + j * h][ff] = v[j];
        }
        __syncthreads();
    }

#pragma unroll
    for (int it = 0; it < 2; it++) {
        int c4 = it * 512 + tid;
        int l = c4 >> 1, q = (c4 & 1) * 4;
        float4 v;
        v.x = s[l][q + 0].x * (1.0f / 512.0f);
        v.y = s[l][q + 1].x * (1.0f / 512.0f);
        v.z = s[l][q + 2].x * (1.0f / 512.0f);
        v.w = s[l][q + 3].x * (1.0f / 512.0f);
        if (smix < 0.01f) v = *reinterpret_cast<const float4*>(xp + (size_t)l * FF + q);
        *reinterpret_cast<float4*>(&g_freq[(size_t)b * LF + (size_t)l * FF + f0 + q]) = v;
    }
}

// ---------------- kernel 3: vectorized fused epilogue -----------------------
__global__ __launch_bounds__(256) void epilogue_kernel(
    const float* __restrict__ x,
    const float* __restrict__ bmv, const float* __restrict__ bnv,
    float* __restrict__ out,
    const float* __restrict__ pm, const float* __restrict__ pn,
    const float* __restrict__ psh)
{
    int tid = threadIdx.x;
    int bid = blockIdx.x;
    int b = bid >> 4;
    int wpb = g_wp[b], shb = g_sh[b];

    float maskmul = sigmf_fast(*pm) * 0.3f;
    float noisemul = sigmf_fast(*pn) * 0.05f;
    float ss_ = sigmf(*psh);
    float smix = 1.0f - ss_;
    float wa = fminf(fmaxf(1.0f - smix - ss_, 0.1f), 0.8f);
    float wb = smix * 0.5f, wc = ss_ * 0.5f;
    float tot = wa + wb + wc;
    wa /= tot; wb /= tot; wc /= tot;
    uint2 kn = tf2x32(0u, 42u, 0u, 1u);

#pragma unroll
    for (int it = 0; it < 2; it++) {
        uint32_t e0 = (uint32_t)bid * 2048u + (uint32_t)it * 1024u + (uint32_t)tid * 4u;
        int col0 = (int)(e0 & 32767u);
        int l = col0 >> 6, f = col0 & 63;
        int idx;
        if (shb > 0)      idx = (l >= wpb) ? min(l + shb, LL - 1) : l;
        else if (shb < 0) idx = (l >= wpb + shb && l < LL + shb) ? (l - shb) : l;
        else              idx = l;
        float4 gm4 = *reinterpret_cast<const float4*>(&g_gm[e0]);
        float4 gn4 = *reinterpret_cast<const float4*>(&g_gn[e0]);
        float4 xv4 = *reinterpret_cast<const float4*>(&x[e0]);
        float4 fv4 = *reinterpret_cast<const float4*>(&g_freq[e0]);
        float4 wv4 = *reinterpret_cast<const float4*>(&x[(size_t)b * LF + (size_t)idx * FF + f]);
        float4 sc4 = *reinterpret_cast<const float4*>(&g_scale[b * FF + f]);
        float4 bm4 = *reinterpret_cast<const float4*>(&bmv[col0]);
        float4 bn4 = *reinterpret_cast<const float4*>(&bnv[col0]);
        float nv0 = tf_normal(kn, e0 + 0u);
        float nv1 = tf_normal(kn, e0 + 1u);
        float nv2 = tf_normal(kn, e0 + 2u);
        float nv3 = tf_normal(kn, e0 + 3u);
        float4 o;
        {
            float mask = 1.0f - (1.0f - sigmf_fast(gm4.x + bm4.x)) * maskmul;
            float nm = softplusf_fast(gn4.x + bn4.x);
            o.x = (xv4.x * mask * sc4.x + nv0 * nm * noisemul) * wa + fv4.x * wb + wv4.x * wc;
        }
        {
            float mask = 1.0f - (1.0f - sigmf_fast(gm4.y + bm4.y)) * maskmul;
            float nm = softplusf_fast(gn4.y + bn4.y);
            o.y = (xv4.y * mask * sc4.y + nv1 * nm * noisemul) * wa + fv4.y * wb + wv4.y * wc;
        }
        {
            float mask = 1.0f - (1.0f - sigmf_fast(gm4.z + bm4.z)) * maskmul;
            float nm = softplusf_fast(gn4.z + bn4.z);
            o.z = (xv4.z * mask * sc4.z + nv2 * nm * noisemul) * wa + fv4.z * wb + wv4.z * wc;
        }
        {
            float mask = 1.0f - (1.0f - sigmf_fast(gm4.w + bm4.w)) * maskmul;
            float nm = softplusf_fast(gn4.w + bn4.w);
            o.w = (xv4.w * mask * sc4.w + nv3 * nm * noisemul) * wa + fv4.w * wb + wv4.w * wc;
        }
        *reinterpret_cast<float4*>(&out[e0]) = o;
    }
}

// ---------------- launch ------------------------------------------------------
extern "C" void kernel_launch(void* const* d_in, const int* in_sizes, int n_in,
                              void* d_out, int out_size) {
    const float* x   = (const float*)d_in[0];
    const float* w1  = (const float*)d_in[2];
    const float* b1  = (const float*)d_in[3];
    const float* w2  = (const float*)d_in[4];
    const float* b2  = (const float*)d_in[5];
    const float* w3  = (const float*)d_in[6];
    const float* b3  = (const float*)d_in[7];
    const float* wm  = (const float*)d_in[8];
    const float* bm  = (const float*)d_in[9];
    const float* wn  = (const float*)d_in[10];
    const float* bn  = (const float*)d_in[11];
    const float* ws  = (const float*)d_in[12];
    const float* bs  = (const float*)d_in[13];
    const float* pm  = (const float*)d_in[14];
    const float* pn  = (const float*)d_in[15];
    const float* psh = (const float*)d_in[16];
    const float* psc = (const float*)d_in[17];
    float* out = (float*)d_out;

    cudaFuncSetAttribute(fft_gemm, cudaFuncAttributeMaxDynamicSharedMemorySize, DYN_SMEM);

    mlp_setup<<<257, 256>>>(w1, b1, w2, b2, w3, b3, ws, bs, psh, psc);
    fft_gemm<<<2560, 512, DYN_SMEM>>>(x, wm, wn, psh);
    epilogue_kernel<<<4096, 256>>>(x, bm, bn, out, pm, pn, psh);
}

// round 17
// speedup vs baseline: 1.1423x; 1.1423x over previous
#include <cuda_runtime.h>
#include <cuda_bf16.h>
#include <mma.h>
#include <cstdint>

using namespace nvcuda;

#define BB   256
#define LL   512
#define FF   64
#define LF   32768
#define NTOT 8388608
#define HH   128
#define H2   256
#define ND   64

// ---------------- device globals ----------------
__device__ __align__(16) uint32_t g_h3b[BB * (H2 / 2)];   // h3 bf16: [256 rows][256]
__device__ float  g_scale[BB * FF];
__device__ float  g_freq[NTOT];
__device__ float  g_gm[NTOT];
__device__ float  g_gn[NTOT];
__device__ int    g_wp[BB], g_sh[BB];

// ---------------- threefry2x32 (JAX) ----------------
__device__ __forceinline__ uint2 tf2x32(uint32_t k0, uint32_t k1, uint32_t x0, uint32_t x1) {
    uint32_t k2 = k0 ^ k1 ^ 0x1BD11BDAu;
    x0 += k0; x1 += k1;
#define TFR(r) { x0 += x1; x1 = (x1 << (r)) | (x1 >> (32 - (r))); x1 ^= x0; }
    TFR(13) TFR(15) TFR(26) TFR(6)
    x0 += k1; x1 += k2 + 1u;
    TFR(17) TFR(29) TFR(16) TFR(24)
    x0 += k2; x1 += k0 + 2u;
    TFR(13) TFR(15) TFR(26) TFR(6)
    x0 += k0; x1 += k1 + 3u;
    TFR(17) TFR(29) TFR(16) TFR(24)
    x0 += k1; x1 += k2 + 4u;
    TFR(13) TFR(15) TFR(26) TFR(6)
    x0 += k2; x1 += k0 + 5u;
#undef TFR
    return make_uint2(x0, x1);
}
__device__ __forceinline__ uint32_t tf_bits(uint2 key, uint32_t e) {
    uint2 r = tf2x32(key.x, key.y, 0u, e);
    return r.x ^ r.y;
}
__device__ __forceinline__ float u01_from_bits(uint32_t bits) {
    return __uint_as_float((bits >> 9) | 0x3f800000u) - 1.0f;
}
__device__ __forceinline__ float tf_normal(uint2 key, uint32_t e) {
    float u = u01_from_bits(tf_bits(key, e));
    const float lo = -0.99999994f;
    float v = u * 2.0f + lo;
    v = fmaxf(lo, v);
    return 1.4142135623730951f * erfinvf(v);
}
__device__ __forceinline__ float sigmf(float x)  { return 1.0f / (1.0f + expf(-x)); }
__device__ __forceinline__ float softplusf(float x) { return fmaxf(x, 0.0f) + log1pf(expf(-fabsf(x))); }
__device__ __forceinline__ float sigmf_fast(float x)  { return __fdividef(1.0f, 1.0f + __expf(-x)); }
__device__ __forceinline__ float softplusf_fast(float x) { return fmaxf(x, 0.0f) + __logf(1.0f + __expf(-fabsf(x))); }

__device__ __forceinline__ float2 cadd(float2 a, float2 b) { return make_float2(a.x + b.x, a.y + b.y); }
__device__ __forceinline__ float2 csub(float2 a, float2 b) { return make_float2(a.x - b.x, a.y - b.y); }
__device__ __forceinline__ float2 cmul(float2 a, float2 w) { return make_float2(a.x * w.x - a.y * w.y, a.x * w.y + a.y * w.x); }
__device__ __forceinline__ float2 cmulc(float2 w, float2 b) { return make_float2(w.x * b.x + w.y * b.y, w.x * b.y - w.y * b.x); }

// ---- shared FFT body (radix-8 rounds), parameterized by units-per-thread ----
// nthreads * UPT == 512 units; each unit = one (group, col) pair per round.
template<int UPT, int NT>
__device__ __forceinline__ void fft_body(
    float2 (*s)[9], const float2* tw, int tid, int b, int f0,
    const float* __restrict__ xp, float ratio, float smix, uint2 kf)
{
#pragma unroll
    for (int it = 0; it < (1024 / NT); it++) {       // load: 1024 float4 chunks
        int c4 = it * NT + tid;
        int l = c4 >> 1, q = (c4 & 1) * 4;
        float4 v = *reinterpret_cast<const float4*>(xp + (size_t)l * FF + q);
        s[l][q + 0] = make_float2(v.x, 0.0f);
        s[l][q + 1] = make_float2(v.y, 0.0f);
        s[l][q + 2] = make_float2(v.z, 0.0f);
        s[l][q + 3] = make_float2(v.w, 0.0f);
    }
    __syncthreads();

    // forward DIF radix-8 rounds
#pragma unroll
    for (int st = 0; st < 9; st += 3) {
        const int h4 = 64 >> st;
#pragma unroll
        for (int it = 0; it < UPT; it++) {
            int u = it * NT + tid;
            int ff = u & 7, gi = u >> 3;
            int k = gi & (h4 - 1);
            int g = gi >> (6 - st);
            int p = (g << (9 - st)) + k;
            float2 v[8];
#pragma unroll
            for (int j = 0; j < 8; j++) v[j] = s[p + j * h4][ff];
#pragma unroll
            for (int j = 0; j < 4; j++) {
                float2 a = v[j], bb = v[j + 4];
                v[j]     = cadd(a, bb);
                v[j + 4] = cmul(csub(a, bb), tw[(k + j * h4) << st]);
            }
#pragma unroll
            for (int jj = 0; jj < 4; jj++) {
                int j = (jj >> 1) * 4 + (jj & 1);
                float2 a = v[j], bb = v[j + 2];
                v[j]     = cadd(a, bb);
                v[j + 2] = cmul(csub(a, bb), tw[(k + (j & 1) * h4) << (st + 1)]);
            }
#pragma unroll
            for (int jj = 0; jj < 4; jj++) {
                int j = jj * 2;
                float2 a = v[j], bb = v[j + 1];
                v[j]     = cadd(a, bb);
                v[j + 1] = cmul(csub(a, bb), tw[k << (st + 2)]);
            }
#pragma unroll
            for (int j = 0; j < 8; j++) s[p + j * h4][ff] = v[j];
        }
        __syncthreads();
    }

    // inverse DIT radix-8 rounds; mask fused into first round's load
#pragma unroll
    for (int st = 0; st < 9; st += 3) {
        const int h = 1 << st;
#pragma unroll
        for (int it = 0; it < UPT; it++) {
            int u = it * NT + tid;
            int ff = u & 7, gi = u >> 3;
            int k = gi & (h - 1);
            int g = gi >> st;
            int p = (g << (st + 3)) + k;
            float2 v[8];
#pragma unroll
            for (int j = 0; j < 8; j++) v[j] = s[p + j * h][ff];
            if (st == 0) {
#pragma unroll
                for (int j = 0; j < 8; j++) {
                    int q = p + j;
                    int jn = (int)(__brev((unsigned)q) >> 23);
                    uint32_t e = (uint32_t)b * LF + (uint32_t)jn * FF + (uint32_t)(f0 + ff);
                    if (!(u01_from_bits(tf_bits(kf, e)) > ratio)) v[j] = make_float2(0.0f, 0.0f);
                }
            }
#pragma unroll
            for (int jj = 0; jj < 4; jj++) {
                int j = jj * 2;
                float2 a = v[j];
                float2 t = cmulc(tw[k << (8 - st)], v[j + 1]);
                v[j]     = cadd(a, t);
                v[j + 1] = csub(a, t);
            }
#pragma unroll
            for (int jj = 0; jj < 4; jj++) {
                int j = (jj >> 1) * 4 + (jj & 1);
                float2 a = v[j];
                float2 t = cmulc(tw[(k + (j & 1) * h) << (7 - st)], v[j + 2]);
                v[j]     = cadd(a, t);
                v[j + 2] = csub(a, t);
            }
#pragma unroll
            for (int j = 0; j < 4; j++) {
                float2 a = v[j];
                float2 t = cmulc(tw[(k + j * h) << (6 - st)], v[j + 4]);
                v[j]     = cadd(a, t);
                v[j + 4] = csub(a, t);
            }
#pragma unroll
            for (int j = 0; j < 8; j++) s[p + j * h][ff] = v[j];
        }
        __syncthreads();
    }

#pragma unroll
    for (int it = 0; it < (1024 / NT); it++) {
        int c4 = it * NT + tid;
        int l = c4 >> 1, q = (c4 & 1) * 4;
        float4 v;
        v.x = s[l][q + 0].x * (1.0f / 512.0f);
        v.y = s[l][q + 1].x * (1.0f / 512.0f);
        v.z = s[l][q + 2].x * (1.0f / 512.0f);
        v.w = s[l][q + 3].x * (1.0f / 512.0f);
        if (smix < 0.01f) v = *reinterpret_cast<const float4*>(xp + (size_t)l * FF + q);
        *reinterpret_cast<float4*>(&g_freq[(size_t)b * LF + (size_t)l * FF + f0 + q]) = v;
    }
}

// ---------------- kernel 1: MLP (0..255) + setup (256) + FFT part1 (257..1280)
__global__ __launch_bounds__(256) void mlp_fft1(
    const float* __restrict__ x,
    const float* __restrict__ w1, const float* __restrict__ b1,
    const float* __restrict__ w2, const float* __restrict__ b2,
    const float* __restrict__ w3, const float* __restrict__ b3,
    const float* __restrict__ ws, const float* __restrict__ bs,
    const float* __restrict__ psh, const float* __restrict__ psc)
{
    __shared__ float2 s[512][9];
    __shared__ float2 tw[256];
    __shared__ float zb[ND], h1b[HH], h2b[H2], h3b[H2];
    int tid = threadIdx.x;

    if (blockIdx.x < 256) {
        // ------- MLP path -------
        int m = blockIdx.x, t = tid;
        uint2 kz = tf2x32(0u, 42u, 0u, 0u);
        if (t < ND) zb[t] = tf_normal(kz, (uint32_t)(m * ND + t));
        __syncthreads();
        if (t < HH) {
            float acc = b1[t];
#pragma unroll 8
            for (int k = 0; k < ND; k++) acc = fmaf(zb[k], w1[k * HH + t], acc);
            h1b[t] = acc > 0.0f ? acc : 0.2f * acc;
        }
        __syncthreads();
        {
            float acc = b2[t];
#pragma unroll 8
            for (int k = 0; k < HH; k++) acc = fmaf(h1b[k], w2[k * H2 + t], acc);
            h2b[t] = acc > 0.0f ? acc : 0.2f * acc;
        }
        __syncthreads();
        {
            float acc = b3[t];
#pragma unroll 8
            for (int k = 0; k < H2; k++) acc = fmaf(h2b[k], w3[k * H2 + t], acc);
            h3b[t] = acc > 0.0f ? acc : 0.2f * acc;
        }
        __syncthreads();
        if (t < H2 / 2) {
            __nv_bfloat162 p = __floats2bfloat162_rn(h3b[2 * t], h3b[2 * t + 1]);
            g_h3b[m * (H2 / 2) + t] = *reinterpret_cast<uint32_t*>(&p);
        }
        if (t < FF) {
            float s_scale = sigmf(*psc);
            float acc = bs[t];
#pragma unroll 8
            for (int k = 0; k < H2; k++) acc = fmaf(h3b[k], ws[k * FF + t], acc);
            g_scale[m * FF + t] = 1.0f + (softplusf(acc) - 0.5f) * 0.2f * s_scale;
        }
        return;
    }
    if (blockIdx.x == 256) {
        // ------- setup -------
        float ss_ = sigmf(*psh);
        int ws_ = (int)(51.2f * ss_);
        uint2 kwp = tf2x32(0u, 42u, 0u, 2u);
        uint2 ksh = tf2x32(0u, 42u, 0u, 3u);
        uint2 skwp1 = tf2x32(kwp.x, kwp.y, 0u, 0u);
        uint2 skwp2 = tf2x32(kwp.x, kwp.y, 0u, 1u);
        uint2 sksh1 = tf2x32(ksh.x, ksh.y, 0u, 0u);
        uint2 sksh2 = tf2x32(ksh.x, ksh.y, 0u, 1u);
        {
            uint32_t span = (uint32_t)max(1, (512 - ws_) - ws_);
            uint32_t mult = 65536u % span; mult = (mult * mult) % span;
            uint32_t hi = tf_bits(skwp1, (uint32_t)tid);
            uint32_t lo = tf_bits(skwp2, (uint32_t)tid);
            uint32_t off = ((hi % span) * mult + (lo % span)) % span;
            g_wp[tid] = ws_ + (int)off;
        }
        {
            uint32_t span = (uint32_t)(2 * ws_ + 1); if (span == 0u) span = 1u;
            uint32_t mult = 65536u % span; mult = (mult * mult) % span;
            uint32_t hi = tf_bits(sksh1, (uint32_t)tid);
            uint32_t lo = tf_bits(sksh2, (uint32_t)tid);
            uint32_t off = ((hi % span) * mult + (lo % span)) % span;
            g_sh[tid] = -ws_ + (int)off;
        }
        return;
    }

    // ------- FFT part 1: global fft-block index 0..1023 -------
    float ss_ = sigmf(*psh);
    float smix = 1.0f - ss_;
    float ratio = fminf(smix * 0.1f, 0.5f);
    uint2 kf = tf2x32(0u, 42u, 0u, 4u);
    int bidx = blockIdx.x - 257;
    int b = bidx >> 3;
    int f0 = (bidx & 7) * 8;
    const float* xp = x + (size_t)b * LF + f0;
    {
        float sv, cv;
        sincosf(-6.283185307179586f * (float)tid / 512.0f, &sv, &cv);
        tw[tid] = make_float2(cv, sv);
    }
    fft_body<2, 256>(s, tw, tid, b, f0, xp, ratio, smix, kf);
}

// ---------------- kernel 2: GEMM (0..511) + FFT part2 (512..1535) -----------
#define BPLD 72
#define PAN_BYTES 36864
#define DYN_SMEM  (2 * PAN_BYTES)       // 73728 B

__global__ __launch_bounds__(512, 2) void gemm_fft2(
    const float* __restrict__ x,
    const float* __restrict__ wm, const float* __restrict__ wn,
    const float* __restrict__ psh)
{
    extern __shared__ char smem[];
    int tid = threadIdx.x;

    if (blockIdx.x < 512) {
        // ================= GEMM path =================
        __nv_bfloat16* Bm = reinterpret_cast<__nv_bfloat16*>(smem);
        __nv_bfloat16* Bn = reinterpret_cast<__nv_bfloat16*>(smem + PAN_BYTES);
        int wid = tid >> 5;
        int n0 = blockIdx.x * 64;
        const __nv_bfloat16* Ag = reinterpret_cast<const __nv_bfloat16*>(g_h3b);

#pragma unroll
        for (int i = 0; i < 4; i++) {
            int u = i * 512 + tid;
            int r = u >> 3, c = (u & 7) * 8;
            {
                const float4* src = reinterpret_cast<const float4*>(wm + (size_t)r * LF + n0 + c);
                float4 v0 = src[0], v1 = src[1];
                __nv_bfloat162 p0 = __floats2bfloat162_rn(v0.x, v0.y);
                __nv_bfloat162 p1 = __floats2bfloat162_rn(v0.z, v0.w);
                __nv_bfloat162 p2 = __floats2bfloat162_rn(v1.x, v1.y);
                __nv_bfloat162 p3 = __floats2bfloat162_rn(v1.z, v1.w);
                uint4 pk = make_uint4(*reinterpret_cast<uint32_t*>(&p0), *reinterpret_cast<uint32_t*>(&p1),
                                      *reinterpret_cast<uint32_t*>(&p2), *reinterpret_cast<uint32_t*>(&p3));
                *reinterpret_cast<uint4*>(Bm + r * BPLD + c) = pk;
            }
            {
                const float4* src = reinterpret_cast<const float4*>(wn + (size_t)r * LF + n0 + c);
                float4 v0 = src[0], v1 = src[1];
                __nv_bfloat162 p0 = __floats2bfloat162_rn(v0.x, v0.y);
                __nv_bfloat162 p1 = __floats2bfloat162_rn(v0.z, v0.w);
                __nv_bfloat162 p2 = __floats2bfloat162_rn(v1.x, v1.y);
                __nv_bfloat162 p3 = __floats2bfloat162_rn(v1.z, v1.w);
                uint4 pk = make_uint4(*reinterpret_cast<uint32_t*>(&p0), *reinterpret_cast<uint32_t*>(&p1),
                                      *reinterpret_cast<uint32_t*>(&p2), *reinterpret_cast<uint32_t*>(&p3));
                *reinterpret_cast<uint4*>(Bn + r * BPLD + c) = pk;
            }
        }
        __syncthreads();

#pragma unroll
        for (int gsel = 0; gsel < 2; gsel++) {
            const __nv_bfloat16* Bt = gsel ? Bn : Bm;
            float* dst = gsel ? g_gn : g_gm;
            wmma::fragment<wmma::accumulator, 16, 16, 16, float> acc[4];
#pragma unroll
            for (int ni = 0; ni < 4; ni++) wmma::fill_fragment(acc[ni], 0.0f);
#pragma unroll
            for (int kt = 0; kt < 16; kt++) {
                wmma::fragment<wmma::matrix_a, 16, 16, 16, __nv_bfloat16, wmma::row_major> af;
                wmma::load_matrix_sync(af, Ag + (size_t)(wid * 16) * H2 + kt * 16, H2);
#pragma unroll
                for (int ni = 0; ni < 4; ni++) {
                    wmma::fragment<wmma::matrix_b, 16, 16, 16, __nv_bfloat16, wmma::row_major> bf;
                    wmma::load_matrix_sync(bf, Bt + (size_t)kt * 16 * BPLD + ni * 16, BPLD);
                    wmma::mma_sync(acc[ni], af, bf, acc[ni]);
                }
            }
#pragma unroll
            for (int ni = 0; ni < 4; ni++)
                wmma::store_matrix_sync(dst + (size_t)(wid * 16) * LF + n0 + ni * 16,
                                        acc[ni], LF, wmma::mem_row_major);
        }
        return;
    }

    // ================= FFT part 2: global fft-block index 1024..2047 ========
    float2 (*s)[9] = reinterpret_cast<float2(*)[9]>(smem);
    float2* tw = reinterpret_cast<float2*>(smem + 36864);

    float ss_ = sigmf(*psh);
    float smix = 1.0f - ss_;
    float ratio = fminf(smix * 0.1f, 0.5f);
    uint2 kf = tf2x32(0u, 42u, 0u, 4u);
    int bidx = blockIdx.x + 512;         // = (blockIdx.x - 512) + 1024
    int b = bidx >> 3;
    int f0 = (bidx & 7) * 8;
    const float* xp = x + (size_t)b * LF + f0;
    if (tid < 256) {
        float sv, cv;
        sincosf(-6.283185307179586f * (float)tid / 512.0f, &sv, &cv);
        tw[tid] = make_float2(cv, sv);
    }
    fft_body<1, 512>(s, tw, tid, b, f0, xp, ratio, smix, kf);
}

// ---------------- kernel 3: vectorized fused epilogue -----------------------
__global__ __launch_bounds__(256) void epilogue_kernel(
    const float* __restrict__ x,
    const float* __restrict__ bmv, const float* __restrict__ bnv,
    float* __restrict__ out,
    const float* __restrict__ pm, const float* __restrict__ pn,
    const float* __restrict__ psh)
{
    int tid = threadIdx.x;
    int bid = blockIdx.x;
    int b = bid >> 4;
    int wpb = g_wp[b], shb = g_sh[b];

    float maskmul = sigmf_fast(*pm) * 0.3f;
    float noisemul = sigmf_fast(*pn) * 0.05f;
    float ss_ = sigmf(*psh);
    float smix = 1.0f - ss_;
    float wa = fminf(fmaxf(1.0f - smix - ss_, 0.1f), 0.8f);
    float wb = smix * 0.5f, wc = ss_ * 0.5f;
    float tot = wa + wb + wc;
    wa /= tot; wb /= tot; wc /= tot;
    uint2 kn = tf2x32(0u, 42u, 0u, 1u);

#pragma unroll
    for (int it = 0; it < 2; it++) {
        uint32_t e0 = (uint32_t)bid * 2048u + (uint32_t)it * 1024u + (uint32_t)tid * 4u;
        int col0 = (int)(e0 & 32767u);
        int l = col0 >> 6, f = col0 & 63;
        int idx;
        if (shb > 0)      idx = (l >= wpb) ? min(l + shb, LL - 1) : l;
        else if (shb < 0) idx = (l >= wpb + shb && l < LL + shb) ? (l - shb) : l;
        else              idx = l;
        float4 gm4 = *reinterpret_cast<const float4*>(&g_gm[e0]);
        float4 gn4 = *reinterpret_cast<const float4*>(&g_gn[e0]);
        float4 xv4 = *reinterpret_cast<const float4*>(&x[e0]);
        float4 fv4 = *reinterpret_cast<const float4*>(&g_freq[e0]);
        float4 wv4 = *reinterpret_cast<const float4*>(&x[(size_t)b * LF + (size_t)idx * FF + f]);
        float4 sc4 = *reinterpret_cast<const float4*>(&g_scale[b * FF + f]);
        float4 bm4 = *reinterpret_cast<const float4*>(&bmv[col0]);
        float4 bn4 = *reinterpret_cast<const float4*>(&bnv[col0]);
        float nv0 = tf_normal(kn, e0 + 0u);
        float nv1 = tf_normal(kn, e0 + 1u);
        float nv2 = tf_normal(kn, e0 + 2u);
        float nv3 = tf_normal(kn, e0 + 3u);
        float4 o;
        {
            float mask = 1.0f - (1.0f - sigmf_fast(gm4.x + bm4.x)) * maskmul;
            float nm = softplusf_fast(gn4.x + bn4.x);
            o.x = (xv4.x * mask * sc4.x + nv0 * nm * noisemul) * wa + fv4.x * wb + wv4.x * wc;
        }
        {
            float mask = 1.0f - (1.0f - sigmf_fast(gm4.y + bm4.y)) * maskmul;
            float nm = softplusf_fast(gn4.y + bn4.y);
            o.y = (xv4.y * mask * sc4.y + nv1 * nm * noisemul) * wa + fv4.y * wb + wv4.y * wc;
        }
        {
            float mask = 1.0f - (1.0f - sigmf_fast(gm4.z + bm4.z)) * maskmul;
            float nm = softplusf_fast(gn4.z + bn4.z);
            o.z = (xv4.z * mask * sc4.z + nv2 * nm * noisemul) * wa + fv4.z * wb + wv4.z * wc;
        }
        {
            float mask = 1.0f - (1.0f - sigmf_fast(gm4.w + bm4.w)) * maskmul;
            float nm = softplusf_fast(gn4.w + bn4.w);
            o.w = (xv4.w * mask * sc4.w + nv3 * nm * noisemul) * wa + fv4.w * wb + wv4.w * wc;
        }
        *reinterpret_cast<float4*>(&out[e0]) = o;
    }
}

// ---------------- launch ------------------------------------------------------
extern "C" void kernel_launch(void* const* d_in, const int* in_sizes, int n_in,
                              void* d_out, int out_size) {
    const float* x   = (const float*)d_in[0];
    const float* w1  = (const float*)d_in[2];
    const float* b1  = (const float*)d_in[3];
    const float* w2  = (const float*)d_in[4];
    const float* b2  = (const float*)d_in[5];
    const float* w3  = (const float*)d_in[6];
    const float* b3  = (const float*)d_in[7];
    const float* wm  = (const float*)d_in[8];
    const float* bm  = (const float*)d_in[9];
    const float* wn  = (const float*)d_in[10];
    const float* bn  = (const float*)d_in[11];
    const float* ws  = (const float*)d_in[12];
    const float* bs  = (const float*)d_in[13];
    const float* pm  = (const float*)d_in[14];
    const float* pn  = (const float*)d_in[15];
    const float* psh = (const float*)d_in[16];
    const float* psc = (const float*)d_in[17];
    float* out = (float*)d_out;

    cudaFuncSetAttribute(gemm_fft2, cudaFuncAttributeMaxDynamicSharedMemorySize, DYN_SMEM);

    mlp_fft1<<<1281, 256>>>(x, w1, b1, w2, b2, w3, b3, ws, bs, psh, psc);
    gemm_fft2<<<1536, 512, DYN_SMEM>>>(x, wm, wn, psh);
    epilogue_kernel<<<4096, 256>>>(x, bm, bn, out, pm, pn, psh);
}